// round 15
// baseline (speedup 1.0000x reference)
#include <cuda_runtime.h>

// ---------------- problem constants ----------------
#define D1     4096
#define V2n    2048
#define BN     64
#define K1     25
#define K2     25
#define F1     32
#define F2     64
#define NNZ1   32768
#define NNZ2   16384
#define CH2    2048     // F1*BN
#define FC1F   512
#define FC2F   10
#define FC1FIN 65536
#define KSPLIT 32
// coef = 2/lmax = 1.0 exactly (folded in)

// ---------------- device scratch ----------------
__device__ int   g_cnt1[D1];
__device__ int   g_rp1[D1 + 1];
__device__ int   g_cur1[D1];
__device__ int2  g_e1[NNZ1];                    // packed {col, val-bits} for graph1

__device__ int   g_cnt2[V2n];
__device__ int   g_rp2[V2n + 1];
__device__ int   g_cur2[V2n];
__device__ int   g_ci2[NNZ2];
__device__ float g_cv2[NNZ2];

__device__ float g_T1[K1 * D1 * BN];            // conv1 Cheby states [k][v][b]
__device__ float g_T2[K2 * V2n * CH2];          // conv2 states [k][v][fin*64+b] (400MB)
__device__ float g_W2t[K2 * F1 * F2];           // cl2_W transposed [k][fin][f]
__device__ float g_Y[V2n * BN * F2];            // conv2 GEMM accumulator [v][b][f] (33.5MB)
__device__ float g_P[BN * FC1FIN];              // pooled conv2 out [b][vp*64+f]
__device__ float g_fc1p[KSPLIT * BN * FC1F];
__device__ float g_fc1[BN * FC1F];

// ---------------- f32x2 packed FMA ----------------
__device__ __forceinline__ float2 ffma2(float2 a, float2 b, float2 c) {
    float2 d;
    asm("fma.rn.f32x2 %0, %1, %2, %3;"
        : "=l"(reinterpret_cast<unsigned long long&>(d))
        : "l"(reinterpret_cast<unsigned long long&>(a)),
          "l"(reinterpret_cast<unsigned long long&>(b)),
          "l"(reinterpret_cast<unsigned long long&>(c)));
    return d;
}

// ---------------- CSR build ----------------
__global__ void k_zero() {
    int i = blockIdx.x * blockDim.x + threadIdx.x;
    if (i < D1)  g_cnt1[i] = 0;
    if (i < V2n) g_cnt2[i] = 0;
}

__global__ void k_count(const int* __restrict__ r1, const int* __restrict__ r2) {
    int i = blockIdx.x * blockDim.x + threadIdx.x;
    if (i < NNZ1) atomicAdd(&g_cnt1[r1[i]], 1);
    if (i < NNZ2) atomicAdd(&g_cnt2[r2[i]], 1);
}

__global__ void k_scan() {           // grid = 2 : block 0 -> graph1, block 1 -> graph2
    __shared__ int s[1024];
    int which = blockIdx.x;
    const int* cnt = which ? g_cnt2 : g_cnt1;
    int V  = which ? V2n : D1;
    int* rp  = which ? g_rp2  : g_rp1;
    int* cur = which ? g_cur2 : g_cur1;
    int tid = threadIdx.x;
    int per = V >> 10;
    int base = tid * per;
    int loc[4];
    int sum = 0;
    for (int i = 0; i < per; i++) { loc[i] = cnt[base + i]; sum += loc[i]; }
    s[tid] = sum; __syncthreads();
    for (int off = 1; off < 1024; off <<= 1) {
        int v = (tid >= off) ? s[tid - off] : 0;
        __syncthreads();
        s[tid] += v;
        __syncthreads();
    }
    int run = (tid == 0) ? 0 : s[tid - 1];
    for (int i = 0; i < per; i++) { rp[base + i] = run; cur[base + i] = run; run += loc[i]; }
    if (tid == 1023) rp[V] = run;
}

__global__ void k_scatter(const int* __restrict__ r1, const int* __restrict__ c1,
                          const float* __restrict__ v1,
                          const int* __restrict__ r2, const int* __restrict__ c2,
                          const float* __restrict__ v2) {
    int bid = blockIdx.x, tid = threadIdx.x;
    if (bid < 128) {                       // graph1: NNZ1 = 128*256
        int i = bid * 256 + tid;
        int p = atomicAdd(&g_cur1[r1[i]], 1);
        g_e1[p] = make_int2(c1[i], __float_as_int(v1[i]));
    } else {                               // graph2: NNZ2 = 64*256
        int i = (bid - 128) * 256 + tid;
        int p = atomicAdd(&g_cur2[r2[i]], 1);
        g_ci2[p] = c2[i];
        g_cv2[p] = v2[i];
    }
}

// ---------------- conv1: whole 25-step recurrence in ONE kernel ----------------
// 64 blocks (one per batch column), 512 threads; T_{k-1}/T_{k-2} in smem.
__global__ void __launch_bounds__(512, 1) k_cheb1f(const float* __restrict__ x) {
    __shared__ float sA[D1];
    __shared__ float sB[D1];
    int b = blockIdx.x, tid = threadIdx.x;
    int base = tid * 8;
    int ep[9];
#pragma unroll
    for (int r = 0; r < 9; r++) ep[r] = g_rp1[base + r];

    for (int v = tid; v < D1; v += 512) {
        float xv = x[b * D1 + v];
        sA[v] = xv;
        g_T1[v * BN + b] = xv;               // slice 0
    }
    __syncthreads();

    float* cur = sA;   // T_{k-1}
    float* prv = sB;   // T_{k-2} (garbage at k=1, unused)
    for (int k = 1; k < K1; k++) {
        float* dst = prv;                    // overwrite T_{k-2} in place
        float* T1k = g_T1 + k * (D1 * BN);
#pragma unroll
        for (int r = 0; r < 8; r++) {
            int v = base + r;
            float acc = 0.f;
            for (int e = ep[r]; e < ep[r + 1]; e++) {
                int2 ed = g_e1[e];
                acc = fmaf(__int_as_float(ed.y), cur[ed.x], acc);
            }
            float ls = acc - cur[v];
            float o = (k >= 2) ? (2.f * ls - prv[v]) : ls;
            dst[v] = o;                      // own row only; safe before sync
            T1k[v * BN + b] = o;             // scattered store, ~32B sectors
        }
        __syncthreads();
        float* t = cur; cur = dst; prv = t;
    }
}

// conv1 GEMM + bias + relu + maxpool2 -> T2 slice 0 [v2][fin*64+b]
__global__ void k_conv1_out(const float* __restrict__ W1, const float* __restrict__ b1) {
    __shared__ float sW[F1 * K1];
    __shared__ float sb[F1];
    int tid = threadIdx.x;
    for (int i = tid; i < F1 * K1; i += 256) sW[i] = W1[i];
    if (tid < F1) sb[tid] = b1[tid];
    __syncthreads();
    int v2 = blockIdx.x * 4 + (tid >> 6);
    int b  = tid & 63;
    float t0[K1], t1[K1];
#pragma unroll
    for (int k = 0; k < K1; k++) {
        t0[k] = g_T1[k * (D1 * BN) + (2 * v2) * BN + b];
        t1[k] = g_T1[k * (D1 * BN) + (2 * v2 + 1) * BN + b];
    }
    for (int f = 0; f < F1; f++) {
        float a0 = sb[f], a1 = sb[f];
#pragma unroll
        for (int k = 0; k < K1; k++) {
            float w = sW[f * K1 + k];
            a0 = fmaf(t0[k], w, a0);
            a1 = fmaf(t1[k], w, a1);
        }
        float o = fmaxf(fmaxf(a0, a1), 0.f);
        g_T2[v2 * CH2 + f * BN + b] = o;
    }
}

// transpose cl2_W [64][fin*25+k] -> g_W2t[k][fin][f]
__global__ void k_w2t(const float* __restrict__ W2) {
    int i = blockIdx.x * blockDim.x + threadIdx.x;
    if (i < K2 * F1 * F2) {
        int f   = i & 63;
        int fin = (i >> 6) & 31;
        int k   = i >> 11;
        g_W2t[i] = W2[f * (F1 * K2) + fin * K2 + k];
    }
}

// ---- GEMM slice accumulation body (shared by fused kernel and epilogue) ----
// Block handles node pair (2vp, 2vp+1), slices [kb, ke). acc0/acc1 updated.
__device__ __forceinline__ void gemm_slices(float* sh, int vp, int kb, int ke,
                                            int tid, int b, int fg,
                                            float2* acc0, float2* acc1) {
    float* sT0 = sh;
    float* sT1 = sh + CH2;
    float* sW  = sh + 2 * CH2;
    for (int k = kb; k < ke; k++) {
        const float* Tk = g_T2 + (size_t)k * V2n * CH2;
        for (int i = tid; i < CH2; i += 256) {
            sT0[i] = Tk[(size_t)(2 * vp) * CH2 + i];
            sT1[i] = Tk[(size_t)(2 * vp + 1) * CH2 + i];
        }
        for (int i = tid; i < F1 * F2; i += 256) sW[i] = g_W2t[k * (F1 * F2) + i];
        __syncthreads();
#pragma unroll 4
        for (int fin = 0; fin < F1; fin++) {
            float tv0 = sT0[fin * BN + b];
            float tv1 = sT1[fin * BN + b];
            float2 p0 = make_float2(tv0, tv0);
            float2 p1 = make_float2(tv1, tv1);
            const float2* wrow = reinterpret_cast<const float2*>(&sW[fin * F2 + fg * 16]);
#pragma unroll
            for (int j = 0; j < 8; j++) {
                float2 w = wrow[j];
                acc0[j] = ffma2(p0, w, acc0[j]);
                acc1[j] = ffma2(p1, w, acc1[j]);
            }
        }
        __syncthreads();
    }
}

// ---------------- conv2: cheb step (+ optional GEMM pass blocks) ----------------
// ngemm=0: grid=2048, all blocks cheb step k.
// ngemm=1: grid=3072; bid%3==2 -> GEMM block for slices [k-3,k), else cheb.
__global__ void k_cheb2f(int k, int ngemm, int kbase, int firstpass) {
    __shared__ alignas(16) float sh[2 * CH2 + F1 * F2];   // 24KB
    int bid = blockIdx.x, tid = threadIdx.x;

    int isg = 0, v, vp = 0;
    if (ngemm) {
        if (bid % 3 == 2) { isg = 1; vp = bid / 3; }
        else v = (bid / 3) * 2 + (bid % 3);
    } else v = bid;

    if (!isg) {
        // ---- cheb step ----
        int*   sci = (int*)sh;
        float* scv = sh + 128;
        const float* Tm1 = g_T2 + (size_t)(k - 1) * V2n * CH2;
        float* out = g_T2 + (size_t)k * V2n * CH2 + (size_t)v * CH2;
        float acc[8] = {0.f, 0.f, 0.f, 0.f, 0.f, 0.f, 0.f, 0.f};
        int e0 = g_rp2[v], e1 = g_rp2[v + 1];
        for (int eb = e0; eb < e1; eb += 128) {
            int n = min(128, e1 - eb);
            if (tid < n) { sci[tid] = g_ci2[eb + tid]; scv[tid] = g_cv2[eb + tid]; }
            __syncthreads();
            for (int j = 0; j < n; j++) {
                const float* zr = Tm1 + (size_t)sci[j] * CH2 + tid;
                float w = scv[j];
#pragma unroll
                for (int i = 0; i < 8; i++) acc[i] = fmaf(w, zr[i * 256], acc[i]);
            }
            __syncthreads();
        }
        const float* z1r = Tm1 + (size_t)v * CH2;
        if (k >= 2) {
            const float* z0r = g_T2 + (size_t)(k - 2) * V2n * CH2 + (size_t)v * CH2;
#pragma unroll
            for (int i = 0; i < 8; i++) {
                int c = tid + i * 256;
                out[c] = 2.f * (acc[i] - z1r[c]) - z0r[c];
            }
        } else {
#pragma unroll
            for (int i = 0; i < 8; i++) {
                int c = tid + i * 256;
                out[c] = acc[i] - z1r[c];
            }
        }
    } else {
        // ---- GEMM pass: slices [kbase, kbase+3) into g_Y ----
        int b = tid & 63, fg = tid >> 6;
        float2 acc0[8], acc1[8];
#pragma unroll
        for (int i = 0; i < 8; i++) { acc0[i] = make_float2(0.f, 0.f); acc1[i] = make_float2(0.f, 0.f); }
        gemm_slices(sh, vp, kbase, kbase + 3, tid, b, fg, acc0, acc1);

        float4* y0 = reinterpret_cast<float4*>(g_Y + (size_t)(2 * vp) * (BN * F2) + b * F2 + fg * 16);
        float4* y1 = reinterpret_cast<float4*>(g_Y + (size_t)(2 * vp + 1) * (BN * F2) + b * F2 + fg * 16);
#pragma unroll
        for (int q = 0; q < 4; q++) {
            float4 n0 = make_float4(acc0[2 * q].x, acc0[2 * q].y, acc0[2 * q + 1].x, acc0[2 * q + 1].y);
            float4 n1 = make_float4(acc1[2 * q].x, acc1[2 * q].y, acc1[2 * q + 1].x, acc1[2 * q + 1].y);
            if (!firstpass) {
                float4 o0 = y0[q], o1 = y1[q];
                n0.x += o0.x; n0.y += o0.y; n0.z += o0.z; n0.w += o0.w;
                n1.x += o1.x; n1.y += o1.y; n1.z += o1.z; n1.w += o1.w;
            }
            y0[q] = n0;
            y1[q] = n1;
        }
    }
}

// ---------------- conv2 epilogue: slice 24 + Y + bias + relu + maxpool2 -> P ----------------
__global__ void k_conv2_epi(const float* __restrict__ b2) {
    __shared__ alignas(16) float sh[2 * CH2 + F1 * F2];
    int vp = blockIdx.x, tid = threadIdx.x;
    int b = tid & 63, fg = tid >> 6;
    float2 acc0[8], acc1[8];
#pragma unroll
    for (int i = 0; i < 8; i++) { acc0[i] = make_float2(0.f, 0.f); acc1[i] = make_float2(0.f, 0.f); }
    gemm_slices(sh, vp, K2 - 1, K2, tid, b, fg, acc0, acc1);

    const float4* y0 = reinterpret_cast<const float4*>(g_Y + (size_t)(2 * vp) * (BN * F2) + b * F2 + fg * 16);
    const float4* y1 = reinterpret_cast<const float4*>(g_Y + (size_t)(2 * vp + 1) * (BN * F2) + b * F2 + fg * 16);
#pragma unroll
    for (int q = 0; q < 4; q++) {
        float4 o0 = y0[q], o1 = y1[q];
        acc0[2 * q].x     += o0.x; acc0[2 * q].y     += o0.y;
        acc0[2 * q + 1].x += o0.z; acc0[2 * q + 1].y += o0.w;
        acc1[2 * q].x     += o1.x; acc1[2 * q].y     += o1.y;
        acc1[2 * q + 1].x += o1.z; acc1[2 * q + 1].y += o1.w;
    }
#pragma unroll
    for (int j = 0; j < 8; j++) {
        int f = fg * 16 + 2 * j;
        float bb0 = b2[f], bb1 = b2[f + 1];
        float o0 = fmaxf(fmaxf(acc0[j].x + bb0, acc1[j].x + bb0), 0.f);
        float o1 = fmaxf(fmaxf(acc0[j].y + bb1, acc1[j].y + bb1), 0.f);
        sh[b * 64 + f]     = o0;
        sh[b * 64 + f + 1] = o1;
    }
    __syncthreads();
    for (int o = tid; o < 4096; o += 256) {
        int bb = o >> 6, f = o & 63;
        g_P[(size_t)bb * FC1FIN + vp * 64 + f] = sh[o];
    }
}

// ---------------- FC1: split-K tiled GEMM with f32x2 ----------------
__global__ void k_fc1(const float* __restrict__ W) {
    __shared__ alignas(16) float sP[64 * 34];
    __shared__ alignas(16) float sW[64 * 34];
    int bid = blockIdx.x;
    int jt = bid & 7;
    int ks = bid >> 3;
    int tid = threadIdx.x;
    int jq = tid & 15, bq = tid >> 4;
    float2 acc[4][4];
#pragma unroll
    for (int u = 0; u < 4; u++)
#pragma unroll
        for (int w = 0; w < 4; w++) acc[u][w] = make_float2(0.f, 0.f);

    int ibase0 = ks * (FC1FIN / KSPLIT);
    for (int it = 0; it < FC1FIN / KSPLIT; it += 32) {
        int ib = ibase0 + it;
        for (int o = tid; o < 64 * 32; o += 256) {
            int r = o >> 5, i = o & 31;
            sP[r * 34 + i] = g_P[(size_t)r * FC1FIN + ib + i];
            sW[r * 34 + i] = W[(size_t)(jt * 64 + r) * FC1FIN + ib + i];
        }
        __syncthreads();
#pragma unroll
        for (int i = 0; i < 32; i += 2) {
            float2 pv[4], wv[4];
#pragma unroll
            for (int u = 0; u < 4; u++)
                pv[u] = *reinterpret_cast<const float2*>(&sP[(bq * 4 + u) * 34 + i]);
#pragma unroll
            for (int u = 0; u < 4; u++)
                wv[u] = *reinterpret_cast<const float2*>(&sW[(jq * 4 + u) * 34 + i]);
#pragma unroll
            for (int u = 0; u < 4; u++)
#pragma unroll
                for (int w = 0; w < 4; w++)
                    acc[u][w] = ffma2(pv[u], wv[w], acc[u][w]);
        }
        __syncthreads();
    }
#pragma unroll
    for (int u = 0; u < 4; u++)
#pragma unroll
        for (int w = 0; w < 4; w++) {
            float s = acc[u][w].x + acc[u][w].y;
            int b = bq * 4 + u;
            int j = jt * 64 + jq * 4 + w;
            g_fc1p[(size_t)ks * (BN * FC1F) + b * FC1F + j] = s;
        }
}

__global__ void k_fc1_red(const float* __restrict__ b1) {
    int idx = blockIdx.x * blockDim.x + threadIdx.x;
    float s = 0.f;
#pragma unroll
    for (int ks = 0; ks < KSPLIT; ks++) s += g_fc1p[ks * (BN * FC1F) + idx];
    int j = idx & 511;
    g_fc1[idx] = fmaxf(s + b1[j], 0.f);
}

__global__ void k_fc2(const float* __restrict__ W, const float* __restrict__ bb,
                      float* __restrict__ out) {
    __shared__ float sf[FC1F];
    int b = blockIdx.x;
    int tid = threadIdx.x;
    for (int j = tid; j < FC1F; j += 320) sf[j] = g_fc1[b * FC1F + j];
    __syncthreads();
    int w = tid >> 5, lane = tid & 31;
    if (w < FC2F) {
        float s = 0.f;
        for (int j = lane; j < FC1F; j += 32) s = fmaf(sf[j], W[w * FC1F + j], s);
#pragma unroll
        for (int off = 16; off; off >>= 1) s += __shfl_down_sync(0xffffffff, s, off);
        if (lane == 0) out[b * FC2F + w] = s + bb[w];
    }
}

// ---------------- launch ----------------
extern "C" void kernel_launch(void* const* d_in, const int* in_sizes, int n_in,
                              void* d_out, int out_size) {
    const float* x    = (const float*)d_in[0];
    const int*   l1r  = (const int*)  d_in[1];
    const int*   l1c  = (const int*)  d_in[2];
    const float* l1v  = (const float*)d_in[3];
    const int*   l2r  = (const int*)  d_in[4];
    const int*   l2c  = (const int*)  d_in[5];
    const float* l2v  = (const float*)d_in[6];
    const float* cl1W = (const float*)d_in[7];
    const float* cl1b = (const float*)d_in[8];
    const float* cl2W = (const float*)d_in[9];
    const float* cl2b = (const float*)d_in[10];
    const float* fc1W = (const float*)d_in[11];
    const float* fc1b = (const float*)d_in[12];
    const float* fc2W = (const float*)d_in[13];
    const float* fc2b = (const float*)d_in[14];
    float* out = (float*)d_out;

    // CSR build
    k_zero<<<16, 256>>>();
    k_count<<<128, 256>>>(l1r, l2r);
    k_scan<<<2, 1024>>>();
    k_scatter<<<192, 256>>>(l1r, l1c, l1v, l2r, l2c, l2v);

    // conv1 (single fused recurrence) + output GEMM
    k_cheb1f<<<64, 512>>>(x);
    k_conv1_out<<<512, 256>>>(cl1W, cl1b);

    // conv2: cheb chain with GEMM passes riding every 3rd launch
    k_w2t<<<200, 256>>>(cl2W);
    for (int k = 1; k < K2; k++) {
        if (k % 3 == 0) k_cheb2f<<<3072, 256>>>(k, 1, k - 3, (k == 3) ? 1 : 0);
        else            k_cheb2f<<<2048, 256>>>(k, 0, 0, 0);
    }
    k_conv2_epi<<<1024, 256>>>(cl2b);

    // FC head
    k_fc1<<<256, 256>>>(fc1W);
    k_fc1_red<<<128, 256>>>(fc1b);
    k_fc2<<<64, 320>>>(fc2W, fc2b, out);
}